// round 5
// baseline (speedup 1.0000x reference)
#include <cuda_runtime.h>
#include <math.h>
#include <stdint.h>

// Problem constants
#define LAYERS 4
#define D_     128
#define N_     2048
#define TWON   4096
#define INV_T  5.0f
#define EPS    1e-12f
#define C_EX2  7.21347520444481703076  // (1/T) * log2(e)

#define NCHUNK 32          // 4096 / 128 cols per chunk
#define CHUNK  128
#define SROWB  144         // smem row stride bytes (128 int8 + 16B pad)
#define TILEB  (128 * SROWB)   // 18432

// int->float bias trick constants
#define IBIAS  0x4B400000          // float 12582912.0 = 2^23 + 2^22
__device__ __constant__ float CQ    = (float)(C_EX2 / 16129.0);            // per-int exponent scale
__device__ __constant__ float BIASQ = (float)(12582912.0 * (C_EX2 / 16129.0));
#define QSCALE_INV (1.0f / 16129.0f)   // 1/127^2

// Scratch
__device__ __align__(256) int8_t g_zq[LAYERS * TWON * D_];
__device__ float g_lp[LAYERS * TWON];

// ---------------------------------------------------------------------------
__device__ __forceinline__ uint32_t smem_u32(const void* p) {
    uint32_t a;
    asm("{ .reg .u64 t; cvta.to.shared.u64 t, %1; cvt.u32.u64 %0, t; }" : "=r"(a) : "l"(p));
    return a;
}
__device__ __forceinline__ float ex2f(float x) {
    float r; asm("ex2.approx.ftz.f32 %0, %1;" : "=f"(r) : "f"(x)); return r;
}
#define CP_ASYNC16(dst, src) \
    asm volatile("cp.async.cg.shared.global [%0], [%1], 16;" :: "r"(dst), "l"(src))
#define CP_COMMIT() asm volatile("cp.async.commit_group;" ::: "memory")
#define CP_WAIT(n)  asm volatile("cp.async.wait_group %0;" :: "n"(n) : "memory")

__device__ __forceinline__ void ldsm4(uint32_t* r, uint32_t addr) {
    asm volatile("ldmatrix.sync.aligned.m8n8.x4.shared.b16 {%0,%1,%2,%3}, [%4];"
                 : "=r"(r[0]), "=r"(r[1]), "=r"(r[2]), "=r"(r[3]) : "r"(addr));
}
__device__ __forceinline__ void mma_s8(int* c, const uint32_t* a, const uint32_t* b) {
    asm volatile(
        "mma.sync.aligned.m16n8k32.row.col.s32.s8.s8.s32 "
        "{%0,%1,%2,%3}, {%4,%5,%6,%7}, {%8,%9}, {%0,%1,%2,%3};"
        : "+r"(c[0]), "+r"(c[1]), "+r"(c[2]), "+r"(c[3])
        : "r"(a[0]), "r"(a[1]), "r"(a[2]), "r"(a[3]), "r"(b[0]), "r"(b[1]));
}
// s32 (|s| << 2^22) -> exp2(s * CQ) via integer-bias float trick
__device__ __forceinline__ float exp_int(int s) {
    float f = __int_as_float(s + IBIAS);
    return ex2f(fmaf(f, CQ, -BIASQ));
}

// ---------------------------------------------------------------------------
// Kernel 1: L2-normalize -> int8 (q = round(127*z)). One warp per row.
// ---------------------------------------------------------------------------
__global__ void norm_q_kernel(const float* __restrict__ emb_i,
                              const float* __restrict__ emb_j) {
    int warp = (blockIdx.x * blockDim.x + threadIdx.x) >> 5;
    int lane = threadIdx.x & 31;
    if (warp >= LAYERS * TWON) return;
    int layer = warp >> 12;
    int row   = warp & (TWON - 1);

    const float* src = (row < N_)
        ? (emb_i + ((size_t)layer * N_ + row) * D_)
        : (emb_j + ((size_t)layer * N_ + (row - N_)) * D_);

    float4 v = ((const float4*)src)[lane];
    float s = v.x * v.x + v.y * v.y + v.z * v.z + v.w * v.w;
    #pragma unroll
    for (int o = 16; o > 0; o >>= 1) s += __shfl_xor_sync(0xffffffffu, s, o);

    float inv = 127.0f / fmaxf(sqrtf(s), EPS);
    int q0 = __float2int_rn(v.x * inv);
    int q1 = __float2int_rn(v.y * inv);
    int q2 = __float2int_rn(v.z * inv);
    int q3 = __float2int_rn(v.w * inv);
    uint32_t b = (uint32_t)(q0 & 0xFF) | ((uint32_t)(q1 & 0xFF) << 8)
               | ((uint32_t)(q2 & 0xFF) << 16) | ((uint32_t)(q3 & 0xFF) << 24);
    ((uint32_t*)(g_zq + ((size_t)layer * TWON + row) * D_))[lane] = b;
}

// ---------------------------------------------------------------------------
// Kernel 2: int8 mma.sync fused Gram + exp + row reduction.
// Grid = LAYERS*32 CTAs; block = 256 (8 warps, 2x4 grid: m_w=64, n_w=32).
// A tile in smem (ldmatrix per chunk), B streamed 128-col chunks, double-buffered.
// ---------------------------------------------------------------------------
extern __shared__ char dsm[];

__device__ __forceinline__ void load_tile(const int8_t* Z, int rowBase,
                                          uint32_t base, int tid) {
    #pragma unroll
    for (int i = 0; i < 4; ++i) {
        int idx = i * 256 + tid;           // 1024 16B-segments
        int r = idx >> 3, sc = idx & 7;
        const char* src = (const char*)(Z + (size_t)(rowBase + r) * D_) + sc * 16;
        CP_ASYNC16(base + r * SROWB + sc * 16, src);
    }
}

__global__ void __launch_bounds__(256, 1) sim_mma_kernel() {
    __shared__ float red_d[2][4][64];
    __shared__ float red_g[2][4][64];
    __shared__ float red_p[2][4][64];

    int tid  = threadIdx.x;
    int wid  = tid >> 5;
    int lane = tid & 31;
    int warpRow = wid >> 2;    // 0..1  (64-row slice)
    int warpCol = wid & 3;     // 0..3  (32-col slice)

    int layer   = blockIdx.x >> 5;
    int tile    = blockIdx.x & 31;
    int rowBase = tile * CHUNK;
    const int8_t* Z = g_zq + (size_t)layer * TWON * D_;

    uint32_t sb = (smem_u32(dsm) + 1023) & ~1023u;
    uint32_t aBase = sb;
    uint32_t bBase[2] = { sb + TILEB, sb + 2 * TILEB };

    // Prologue: A tile + B chunk 0
    load_tile(Z, rowBase, aBase, tid);
    load_tile(Z, 0, bBase[0], tid);
    CP_COMMIT();

    // ldmatrix per-lane address components (SROWB=144 -> 4r mod 32 banks, clean)
    uint32_t laneA = (uint32_t)((lane & 7) * SROWB + ((lane >> 3) & 1) * (8 * SROWB)
                                + ((lane >> 4) & 1) * 16);
    uint32_t laneB = (uint32_t)((lane & 7) * SROWB + ((lane >> 3) & 1) * 16
                                + ((lane >> 4) & 1) * (8 * SROWB));
    uint32_t aAddr  = aBase + (uint32_t)(warpRow * 64 * SROWB) + laneA;
    uint32_t bAddr0 = bBase[0] + (uint32_t)(warpCol * 32 * SROWB) + laneB;
    uint32_t bAddr1 = bBase[1] + (uint32_t)(warpCol * 32 * SROWB) + laneB;

    int acc[4][4][4];
    #pragma unroll
    for (int mt = 0; mt < 4; ++mt)
        #pragma unroll
        for (int nt = 0; nt < 4; ++nt)
            #pragma unroll
            for (int ci = 0; ci < 4; ++ci) acc[mt][nt][ci] = 0;

    float dsum[8];
    int   sdg[8], sps[8];
    #pragma unroll
    for (int i = 0; i < 8; ++i) { dsum[i] = 0.f; sdg[i] = 0; sps[i] = 0; }

    int rowT = rowBase + warpRow * 64 + (lane >> 2);   // + mt*16 + 8*(ci>>1)
    int colT = warpCol * 32 + (lane & 3) * 2;          // + nt*8 + (ci&1) + cb

    int diagChunk = tile;
    int posChunk  = tile ^ (N_ / CHUNK);               // tile ^ 16

    for (int ct = 0; ct < NCHUNK; ++ct) {
        if (ct + 1 < NCHUNK) {
            load_tile(Z, (ct + 1) * CHUNK, bBase[(ct + 1) & 1], tid);
            CP_COMMIT();
            CP_WAIT(1);
        } else {
            CP_WAIT(0);
        }
        __syncthreads();

        uint32_t bA = (ct & 1) ? bAddr1 : bAddr0;

        // K=128 in 4 k-tiles of 32
        #pragma unroll
        for (int kt = 0; kt < 4; ++kt) {
            uint32_t aF[4][4];
            uint32_t bF[4][2];
            #pragma unroll
            for (int mt = 0; mt < 4; ++mt)
                ldsm4(aF[mt], aAddr + (uint32_t)(mt * 16 * SROWB + kt * 32));
            #pragma unroll
            for (int np = 0; np < 2; ++np) {
                uint32_t t[4];
                ldsm4(t, bA + (uint32_t)(np * 16 * SROWB + kt * 32));
                bF[2 * np][0] = t[0];     bF[2 * np][1] = t[1];
                bF[2 * np + 1][0] = t[2]; bF[2 * np + 1][1] = t[3];
            }
            #pragma unroll
            for (int mt = 0; mt < 4; ++mt)
                #pragma unroll
                for (int nt = 0; nt < 4; ++nt)
                    mma_s8(acc[mt][nt], aF[mt], bF[nt]);
        }

        // Epilogue: exp-accumulate; capture diag/pos only in the 2 relevant chunks
        int cb = ct * CHUNK;
        bool chk = (ct == diagChunk) || (ct == posChunk);
        if (chk) {
            #pragma unroll
            for (int mt = 0; mt < 4; ++mt)
                #pragma unroll
                for (int nt = 0; nt < 4; ++nt)
                    #pragma unroll
                    for (int ci = 0; ci < 4; ++ci) {
                        int s = acc[mt][nt][ci];
                        int ri = mt * 2 + (ci >> 1);
                        int grow = rowT + mt * 16 + (ci >> 1) * 8;
                        int gcol = cb + colT + nt * 8 + (ci & 1);
                        dsum[ri] += exp_int(s);
                        if (gcol == grow)        sdg[ri] = s;
                        if (gcol == (grow ^ N_)) sps[ri] = s;
                        acc[mt][nt][ci] = 0;
                    }
        } else {
            #pragma unroll
            for (int mt = 0; mt < 4; ++mt)
                #pragma unroll
                for (int nt = 0; nt < 4; ++nt)
                    #pragma unroll
                    for (int ci = 0; ci < 4; ++ci) {
                        int s = acc[mt][nt][ci];
                        dsum[mt * 2 + (ci >> 1)] += exp_int(s);
                        acc[mt][nt][ci] = 0;
                    }
        }
        __syncthreads();
    }

    // Reduce across lane&3 (cols within warp); convert captured ints to float
    float sdgf[8], spsf[8];
    #pragma unroll
    for (int ri = 0; ri < 8; ++ri) {
        sdgf[ri] = (float)sdg[ri] * QSCALE_INV;
        spsf[ri] = (float)sps[ri] * QSCALE_INV;
    }
    #pragma unroll
    for (int ri = 0; ri < 8; ++ri) {
        #pragma unroll
        for (int o = 1; o <= 2; o <<= 1) {
            dsum[ri] += __shfl_xor_sync(0xffffffffu, dsum[ri], o);
            sdgf[ri] += __shfl_xor_sync(0xffffffffu, sdgf[ri], o);
            spsf[ri] += __shfl_xor_sync(0xffffffffu, spsf[ri], o);
        }
    }
    if ((lane & 3) == 0) {
        #pragma unroll
        for (int ri = 0; ri < 8; ++ri) {
            int mt = ri >> 1, hi = ri & 1;
            int rloc = mt * 16 + (lane >> 2) + 8 * hi;
            red_d[warpRow][warpCol][rloc] = dsum[ri];
            red_g[warpRow][warpCol][rloc] = sdgf[ri];
            red_p[warpRow][warpCol][rloc] = spsf[ri];
        }
    }
    __syncthreads();

    if (tid < 128) {
        int wr = tid >> 6, rl = tid & 63;
        float d = 0.f, sg = 0.f, sp = 0.f;
        #pragma unroll
        for (int wc = 0; wc < 4; ++wc) {
            d  += red_d[wr][wc][rl];
            sg += red_g[wr][wc][rl];
            sp += red_p[wr][wc][rl];
        }
        float denom = d - ex2f(sg * (float)C_EX2);  // exclude diagonal
        g_lp[layer * TWON + rowBase + tid] = logf(denom) - sp * INV_T;
    }
}

// ---------------------------------------------------------------------------
// Kernel 3: deterministic final reduction with joint_valid mask.
// ---------------------------------------------------------------------------
__global__ void finalize_kernel(const float* __restrict__ joint_valid,
                                float* __restrict__ out) {
    __shared__ float s1[256];
    __shared__ float s2[256];
    int tid = threadIdx.x;

    float total = 0.f;
    for (int idx = tid; idx < LAYERS * TWON; idx += 256) {
        int row = idx & (TWON - 1);
        total += g_lp[idx] * joint_valid[row & (N_ - 1)];
    }
    float an = 0.f;
    for (int idx = tid; idx < N_; idx += 256) an += joint_valid[idx];

    s1[tid] = total;
    s2[tid] = an;
    __syncthreads();
    for (int s = 128; s > 0; s >>= 1) {
        if (tid < s) { s1[tid] += s1[tid + s]; s2[tid] += s2[tid + s]; }
        __syncthreads();
    }
    if (tid == 0) out[0] = s1[0] / (2.0f * s2[0]);
}

// ---------------------------------------------------------------------------
extern "C" void kernel_launch(void* const* d_in, const int* in_sizes, int n_in,
                              void* d_out, int out_size) {
    const float* emb_i       = (const float*)d_in[0];
    const float* emb_j       = (const float*)d_in[1];
    const float* joint_valid = (const float*)d_in[2];
    float* out = (float*)d_out;
    (void)in_sizes; (void)n_in; (void)out_size;

    const int SIM_SMEM = 1024 + 3 * TILEB;   // A tile + 2 B buffers = 56320 B
    cudaFuncSetAttribute(sim_mma_kernel, cudaFuncAttributeMaxDynamicSharedMemorySize, SIM_SMEM);

    norm_q_kernel<<<(LAYERS * TWON) / 8, 256>>>(emb_i, emb_j);
    sim_mma_kernel<<<LAYERS * 32, 256, SIM_SMEM>>>();
    finalize_kernel<<<1, 256>>>(joint_valid, out);
}

// round 6
// speedup vs baseline: 2.3446x; 2.3446x over previous
#include <cuda_runtime.h>
#include <cuda_bf16.h>
#include <math.h>
#include <stdint.h>

// Problem constants
#define LAYERS 4
#define D_     128
#define N_     2048
#define TWON   4096
#define INV_T  5.0f
#define EPS    1e-12f
#define C_EX2  7.21347520444481703076f   // (1/T) * log2(e)

#define NCHUNK 32          // 4096 / 128 cols per chunk
#define CHUNK  128
#define SROWB  272         // smem row stride bytes (128 bf16 + 16B pad)
#define TILEB  (128 * SROWB)
#define NBUF   3

// Scratch
__device__ __align__(256) __nv_bfloat16 g_zb[LAYERS * TWON * D_];
__device__ float g_lp[LAYERS * TWON];

// ---------------------------------------------------------------------------
__device__ __forceinline__ uint32_t smem_u32(const void* p) {
    uint32_t a;
    asm("{ .reg .u64 t; cvta.to.shared.u64 t, %1; cvt.u32.u64 %0, t; }" : "=r"(a) : "l"(p));
    return a;
}
__device__ __forceinline__ float ex2f(float x) {
    float r; asm("ex2.approx.ftz.f32 %0, %1;" : "=f"(r) : "f"(x)); return r;
}
#define CP_ASYNC16(dst, src) \
    asm volatile("cp.async.cg.shared.global [%0], [%1], 16;" :: "r"(dst), "l"(src))
#define CP_COMMIT() asm volatile("cp.async.commit_group;" ::: "memory")
#define CP_WAIT(n)  asm volatile("cp.async.wait_group %0;" :: "n"(n) : "memory")

__device__ __forceinline__ void ldsm4(uint32_t* r, uint32_t addr) {
    asm volatile("ldmatrix.sync.aligned.m8n8.x4.shared.b16 {%0,%1,%2,%3}, [%4];"
                 : "=r"(r[0]), "=r"(r[1]), "=r"(r[2]), "=r"(r[3]) : "r"(addr));
}
__device__ __forceinline__ void mma_bf16(float* c, const uint32_t* a, const uint32_t* b) {
    asm volatile(
        "mma.sync.aligned.m16n8k16.row.col.f32.bf16.bf16.f32 "
        "{%0,%1,%2,%3}, {%4,%5,%6,%7}, {%8,%9}, {%0,%1,%2,%3};"
        : "+f"(c[0]), "+f"(c[1]), "+f"(c[2]), "+f"(c[3])
        : "r"(a[0]), "r"(a[1]), "r"(a[2]), "r"(a[3]), "r"(b[0]), "r"(b[1]));
}

// ---------------------------------------------------------------------------
// Kernel 1: L2-normalize -> bf16. One warp per row.
// ---------------------------------------------------------------------------
__global__ void norm_bf16_kernel(const float* __restrict__ emb_i,
                                 const float* __restrict__ emb_j) {
    int warp = (blockIdx.x * blockDim.x + threadIdx.x) >> 5;
    int lane = threadIdx.x & 31;
    if (warp >= LAYERS * TWON) return;
    int layer = warp >> 12;
    int row   = warp & (TWON - 1);

    const float* src = (row < N_)
        ? (emb_i + ((size_t)layer * N_ + row) * D_)
        : (emb_j + ((size_t)layer * N_ + (row - N_)) * D_);

    float4 v = ((const float4*)src)[lane];
    float s = v.x * v.x + v.y * v.y + v.z * v.z + v.w * v.w;
    #pragma unroll
    for (int o = 16; o > 0; o >>= 1) s += __shfl_xor_sync(0xffffffffu, s, o);

    float inv = 1.0f / fmaxf(sqrtf(s), EPS);
    uint2 u;
    u.x = (uint32_t)__bfloat16_as_ushort(__float2bfloat16(v.x * inv))
        | ((uint32_t)__bfloat16_as_ushort(__float2bfloat16(v.y * inv)) << 16);
    u.y = (uint32_t)__bfloat16_as_ushort(__float2bfloat16(v.z * inv))
        | ((uint32_t)__bfloat16_as_ushort(__float2bfloat16(v.w * inv)) << 16);
    ((uint2*)(g_zb + ((size_t)layer * TWON + row) * D_))[lane] = u;
}

// ---------------------------------------------------------------------------
// Kernel 2: fused Gram + exp + row reduction (mma.sync bf16).
// Grid = LAYERS*32; block = 256 (8 warps, 4x2 warp grid: m_w=32, n_w=64).
// A fragments register-resident (loaded once, 64 regs). B streamed in 128-col
// chunks through a 3-buffer cp.async ring (one __syncthreads per chunk).
// ---------------------------------------------------------------------------
extern __shared__ char dsm[];

__device__ __forceinline__ void load_tile(const __nv_bfloat16* Z, int rowBase,
                                          uint32_t base, int tid) {
    #pragma unroll
    for (int i = 0; i < 8; ++i) {
        int idx = i * 256 + tid;
        int r = idx >> 4, sc = idx & 15;
        const char* src = (const char*)(Z + (size_t)(rowBase + r) * D_) + sc * 16;
        CP_ASYNC16(base + r * SROWB + sc * 16, src);
    }
}

__global__ void __launch_bounds__(256, 1) sim_mma_kernel() {
    __shared__ float red_d[2][128];
    __shared__ float red_g[2][128];
    __shared__ float red_p[2][128];

    int tid  = threadIdx.x;
    int wid  = tid >> 5;
    int lane = tid & 31;
    int warpRow = wid & 3;      // 4 row slices of 32
    int warpCol = wid >> 2;     // 2 col slices of 64

    int layer   = blockIdx.x >> 5;
    int tile    = blockIdx.x & 31;
    int rowBase = tile * CHUNK;
    const __nv_bfloat16* Z = g_zb + (size_t)layer * TWON * D_;

    uint32_t sb = (smem_u32(dsm) + 1023) & ~1023u;
    uint32_t aBase = sb;
    uint32_t bBase[NBUF] = { sb + TILEB, sb + 2 * TILEB, sb + 3 * TILEB };

    // Prologue: A tile (group0) then B chunk 0 (group1)
    load_tile(Z, rowBase, aBase, tid);
    CP_COMMIT();
    load_tile(Z, 0, bBase[0], tid);
    CP_COMMIT();

    uint32_t laneA = (uint32_t)((lane & 7) * SROWB + ((lane >> 3) & 1) * (8 * SROWB)
                                + ((lane >> 4) & 1) * 16);
    uint32_t laneB = (uint32_t)((lane & 7) * SROWB + ((lane >> 3) & 1) * 16
                                + ((lane >> 4) & 1) * (8 * SROWB));
    uint32_t aAddr = aBase + (uint32_t)(warpRow * 32 * SROWB) + laneA;

    CP_WAIT(1);                 // A done
    __syncthreads();

    // A fragments -> registers (64 regs), reused across all 32 chunks
    uint32_t aF[2][8][4];
    #pragma unroll
    for (int mt = 0; mt < 2; ++mt)
        #pragma unroll
        for (int kt = 0; kt < 8; ++kt)
            ldsm4(aF[mt][kt], aAddr + (uint32_t)(mt * 16 * SROWB + kt * 32));

    float acc[2][8][4];
    #pragma unroll
    for (int mt = 0; mt < 2; ++mt)
        #pragma unroll
        for (int nt = 0; nt < 8; ++nt)
            #pragma unroll
            for (int ci = 0; ci < 4; ++ci) acc[mt][nt][ci] = 0.f;

    float dsum[4], sdg[4], sps[4];
    #pragma unroll
    for (int i = 0; i < 4; ++i) { dsum[i] = 0.f; sdg[i] = 0.f; sps[i] = 0.f; }

    int rowT     = rowBase + warpRow * 32 + (lane >> 2);  // + mt*16 + 8*(ci>>1)
    int colTbase = warpCol * 64 + (lane & 3) * 2;         // + nt*8 + (ci&1) + cb

    int bufIdx[NBUF];   // ring indices precomputed mod 3
    #pragma unroll
    for (int i = 0; i < NBUF; ++i) bufIdx[i] = i;

    for (int ct = 0; ct < NCHUNK; ++ct) {
        int cur = ct % NBUF;
        if (ct + 1 < NCHUNK) {
            load_tile(Z, (ct + 1) * CHUNK, bBase[(ct + 1) % NBUF], tid);
            CP_COMMIT();
            CP_WAIT(1);
        } else {
            CP_WAIT(0);
        }
        __syncthreads();       // B(ct) ready; also fences prior-iteration reads

        uint32_t bA = bBase[cur] + (uint32_t)(warpCol * 64 * SROWB) + laneB;
        #pragma unroll
        for (int kt = 0; kt < 8; ++kt) {
            uint32_t bF[8][2];
            #pragma unroll
            for (int np = 0; np < 4; ++np) {
                uint32_t t[4];
                ldsm4(t, bA + (uint32_t)(np * 16 * SROWB + kt * 32));
                bF[2 * np][0] = t[0];     bF[2 * np][1] = t[1];
                bF[2 * np + 1][0] = t[2]; bF[2 * np + 1][1] = t[3];
            }
            #pragma unroll
            for (int mt = 0; mt < 2; ++mt)
                #pragma unroll
                for (int nt = 0; nt < 8; ++nt)
                    mma_bf16(acc[mt][nt], aF[mt][kt], bF[nt]);
        }

        // Epilogue: exp-accumulate; capture diag/pos only in the 2 relevant chunks
        int cb = ct * CHUNK;
        bool chk = (ct == tile) || (ct == (tile ^ (N_ / CHUNK)));
        if (chk) {
            #pragma unroll
            for (int mt = 0; mt < 2; ++mt)
                #pragma unroll
                for (int nt = 0; nt < 8; ++nt)
                    #pragma unroll
                    for (int ci = 0; ci < 4; ++ci) {
                        float s = acc[mt][nt][ci];
                        int ri = mt * 2 + (ci >> 1);
                        int grow = rowT + mt * 16 + (ci >> 1) * 8;
                        int gcol = cb + colTbase + nt * 8 + (ci & 1);
                        dsum[ri] += ex2f(s * C_EX2);
                        if (gcol == grow)        sdg[ri] = s;
                        if (gcol == (grow ^ N_)) sps[ri] = s;
                        acc[mt][nt][ci] = 0.f;
                    }
        } else {
            #pragma unroll
            for (int mt = 0; mt < 2; ++mt)
                #pragma unroll
                for (int nt = 0; nt < 8; ++nt)
                    #pragma unroll
                    for (int ci = 0; ci < 4; ++ci) {
                        float s = acc[mt][nt][ci];
                        dsum[mt * 2 + (ci >> 1)] += ex2f(s * C_EX2);
                        acc[mt][nt][ci] = 0.f;
                    }
        }
    }

    // Reduce across lane&3 (4 lanes covering col groups)
    #pragma unroll
    for (int ri = 0; ri < 4; ++ri) {
        #pragma unroll
        for (int o = 1; o <= 2; o <<= 1) {
            dsum[ri] += __shfl_xor_sync(0xffffffffu, dsum[ri], o);
            sdg[ri]  += __shfl_xor_sync(0xffffffffu, sdg[ri], o);
            sps[ri]  += __shfl_xor_sync(0xffffffffu, sps[ri], o);
        }
    }
    if ((lane & 3) == 0) {
        #pragma unroll
        for (int ri = 0; ri < 4; ++ri) {
            int mt = ri >> 1, h = ri & 1;
            int rloc = warpRow * 32 + mt * 16 + h * 8 + (lane >> 2);
            red_d[warpCol][rloc] = dsum[ri];
            red_g[warpCol][rloc] = sdg[ri];
            red_p[warpCol][rloc] = sps[ri];
        }
    }
    __syncthreads();

    if (tid < 128) {
        float d  = red_d[0][tid] + red_d[1][tid];
        float sg = red_g[0][tid] + red_g[1][tid];
        float sp = red_p[0][tid] + red_p[1][tid];
        float denom = d - ex2f(sg * C_EX2);   // exclude diagonal
        g_lp[layer * TWON + rowBase + tid] = logf(denom) - sp * INV_T;
    }
}

// ---------------------------------------------------------------------------
// Kernel 3: deterministic final reduction with joint_valid mask.
// ---------------------------------------------------------------------------
__global__ void finalize_kernel(const float* __restrict__ joint_valid,
                                float* __restrict__ out) {
    __shared__ float s1[256];
    __shared__ float s2[256];
    int tid = threadIdx.x;

    float total = 0.f;
    for (int idx = tid; idx < LAYERS * TWON; idx += 256) {
        int row = idx & (TWON - 1);
        total += g_lp[idx] * joint_valid[row & (N_ - 1)];
    }
    float an = 0.f;
    for (int idx = tid; idx < N_; idx += 256) an += joint_valid[idx];

    s1[tid] = total;
    s2[tid] = an;
    __syncthreads();
    for (int s = 128; s > 0; s >>= 1) {
        if (tid < s) { s1[tid] += s1[tid + s]; s2[tid] += s2[tid + s]; }
        __syncthreads();
    }
    if (tid == 0) out[0] = s1[0] / (2.0f * s2[0]);
}

// ---------------------------------------------------------------------------
extern "C" void kernel_launch(void* const* d_in, const int* in_sizes, int n_in,
                              void* d_out, int out_size) {
    const float* emb_i       = (const float*)d_in[0];
    const float* emb_j       = (const float*)d_in[1];
    const float* joint_valid = (const float*)d_in[2];
    float* out = (float*)d_out;
    (void)in_sizes; (void)n_in; (void)out_size;

    const int SIM_SMEM = 1024 + (1 + NBUF) * TILEB;   // A + 3 B buffers = 140288 B
    cudaFuncSetAttribute(sim_mma_kernel, cudaFuncAttributeMaxDynamicSharedMemorySize, SIM_SMEM);

    norm_bf16_kernel<<<(LAYERS * TWON) / 8, 256>>>(emb_i, emb_j);
    sim_mma_kernel<<<LAYERS * 32, 256, SIM_SMEM>>>();
    finalize_kernel<<<1, 256>>>(joint_valid, out);
}